// round 15
// baseline (speedup 1.0000x reference)
#include <cuda_runtime.h>
#include <cuda_bf16.h>
#include <cuda_fp16.h>
#include <math.h>
#include <stdint.h>

typedef unsigned long long ull;

#define QN 48
#define KN 48
#define SS 192
#define DH 512
#define NL 3
#define DFFN 2048
#define NP (QN*KN)   /* 2304 */
#define KC 512
#define ROWB 1024    /* bytes per row = KC * 2 */

#define AELEM (NL*QN*SS*DH)
#define CA_U4 (AELEM/8)
#define W1_U4 (NL*DH*DH/8)
#define W2_U4 (NL*DFFN*SS/8)
#define PREP_N (2*CA_U4 + W1_U4 + W2_U4)

// ---------------- scratch (device globals) ----------------
__device__ uint4  g_Qc[(size_t)NL*QN*SS*ROWB/16];
__device__ uint4  g_Kc[(size_t)NL*KN*SS*ROWB/16];
__device__ __align__(16) __half g_Mh[AELEM];
__device__ __align__(16) __half g_Fh[AELEM];
__device__ __align__(16) __half g_W1h[NL*DH*DH];
__device__ __align__(16) __half g_W2h[NL*DFFN*SS];
__device__ __align__(16) float g_GT[NL * SS * SS];
__device__ float  g_Xr[(size_t)NL * NP * 2 * SS];
__device__ __align__(16) __half g_Xh[(size_t)NL * NP * 2 * SS];
__device__ float  g_Z [NL * NP * 2];

__device__ __forceinline__ uint32_t smem_u32(const void* p) {
    uint32_t a;
    asm("{ .reg .u64 t; cvta.to.shared.u64 t, %1; cvt.u32.u64 %0, t; }" : "=r"(a) : "l"(p));
    return a;
}

// ---------------- mma / ldmatrix wrappers ----------------
__device__ __forceinline__ void mma_fp16(float* d, const uint32_t* a, uint32_t b0, uint32_t b1) {
    asm volatile("mma.sync.aligned.m16n8k16.row.col.f32.f16.f16.f32 "
                 "{%0,%1,%2,%3}, {%4,%5,%6,%7}, {%8,%9}, {%0,%1,%2,%3};"
                 : "+f"(d[0]), "+f"(d[1]), "+f"(d[2]), "+f"(d[3])
                 : "r"(a[0]), "r"(a[1]), "r"(a[2]), "r"(a[3]), "r"(b0), "r"(b1));
}
__device__ __forceinline__ void ldsm_x4(uint32_t* r, uint32_t addr) {
    asm volatile("ldmatrix.sync.aligned.m8n8.x4.shared.b16 {%0,%1,%2,%3}, [%4];"
                 : "=r"(r[0]), "=r"(r[1]), "=r"(r[2]), "=r"(r[3]) : "r"(addr));
}

// ---------------- kernel 1: prep ----------------
__device__ __forceinline__ void cvt8(const float* __restrict__ src, __half* dst, int u) {
    float4 f0 = ((const float4*)src)[u * 2];
    float4 f1 = ((const float4*)src)[u * 2 + 1];
    __half2 a0 = __floats2half2_rn(f0.x, f0.y);
    __half2 a1 = __floats2half2_rn(f0.z, f0.w);
    __half2 a2 = __floats2half2_rn(f1.x, f1.y);
    __half2 a3 = __floats2half2_rn(f1.z, f1.w);
    uint4 v;
    v.x = *reinterpret_cast<uint32_t*>(&a0);
    v.y = *reinterpret_cast<uint32_t*>(&a1);
    v.z = *reinterpret_cast<uint32_t*>(&a2);
    v.w = *reinterpret_cast<uint32_t*>(&a3);
    ((uint4*)dst)[u] = v;
}

__global__ void prep_kernel(const float* __restrict__ mem, const float* __restrict__ feat,
                            const float* __restrict__ w1, const float* __restrict__ w2,
                            const float* __restrict__ se)
{
    int idx = blockIdx.x * blockDim.x + threadIdx.x;
    if (idx < CA_U4)                       cvt8(mem,  g_Mh,  idx);
    else if (idx < 2*CA_U4)                cvt8(feat, g_Fh,  idx - CA_U4);
    else if (idx < 2*CA_U4 + W1_U4)        cvt8(w1,   g_W1h, idx - 2*CA_U4);
    else if (idx < PREP_N)                 cvt8(w2,   g_W2h, idx - 2*CA_U4 - W1_U4);
    if (idx < NL * SS * SS) {
        int i = idx / (SS * SS);
        int rem = idx - i * SS * SS;
        int t = rem / SS, s = rem - t * SS;
        g_GT[idx] = 1.0f / (1.0f + expf(-se[i * SS * SS + s * SS + t]));
    }
    if (idx < NL * NP * 2) g_Z[idx] = 0.0f;
}

// ---------------- kernel 2: projection GEMM (HMMA, fp16 in, both dsts) ----------------
#define PCH 8
#define PSTG 32768

__global__ void __launch_bounds__(256)
proj_mma_kernel(const float* __restrict__ bias)
{
    extern __shared__ __align__(128) char psm[];
    const int z = blockIdx.z;
    const int i = (z < NL) ? z : z - NL;
    const int dst = (z >= NL);
    const __half* Ah = (dst ? g_Fh : g_Mh) + i * DH;
    const __half* Wh = g_W1h + (size_t)i * DH * DH;
    const float* bb = bias + i * DH;
    const int LDA = NL * DH;
    char* outBase = (char*)(dst ? g_Kc : g_Qc) + (size_t)(i * QN * SS) * ROWB;
    const int m0 = blockIdx.y * 128, n0 = blockIdx.x * 128;
    const int tid = threadIdx.x, wid = tid >> 5, lane = tid & 31;
    uint32_t sb = smem_u32(psm);
    const int mw = wid >> 2, nw = wid & 3;
    const int m0w = mw * 64, n0w = nw * 32;

    uint32_t baseA[4], baseB[2];
#pragma unroll
    for (int mi = 0; mi < 4; mi++) {
        uint32_t row = (uint32_t)(m0w + mi * 16 + (lane & 15));
        uint32_t off = row * 128 + ((lane >> 4) << 4);
        baseA[mi] = off ^ ((off >> 3) & 0x70);
    }
#pragma unroll
    for (int nj = 0; nj < 2; nj++) {
        uint32_t row = (uint32_t)(n0w + nj * 16 + (lane & 7) + ((lane >> 4) << 3));
        uint32_t off = row * 128 + (((lane >> 3) & 1) << 4);
        baseB[nj] = 16384u + (off ^ ((off >> 3) & 0x70));
    }

    float acc[4][4][4];
#pragma unroll
    for (int mi = 0; mi < 4; mi++)
#pragma unroll
        for (int n8 = 0; n8 < 4; n8++)
#pragma unroll
            for (int j = 0; j < 4; j++) acc[mi][n8][j] = 0.0f;

    uint4 stg[8];
    auto load_chunk = [&](int c) {
        const int co0 = c * 64;
#pragma unroll
        for (int u = 0; u < 8; u++) {
            int idx = tid + u * 256;
            int isW = idx >= 1024;
            int j = idx & 1023;
            int r = j >> 3, g = j & 7;
            const __half* src = isW ? (Wh + (size_t)(n0 + r) * DH  + co0 + g * 8)
                                    : (Ah + (size_t)(m0 + r) * LDA + co0 + g * 8);
            stg[u] = *(const uint4*)src;
        }
    };
    auto store_chunk = [&](int buf) {
#pragma unroll
        for (int u = 0; u < 8; u++) {
            int idx = tid + u * 256;
            int isW = idx >= 1024;
            int j = idx & 1023;
            int r = j >> 3, g = j & 7;
            uint32_t off = (uint32_t)(r * 128 + g * 16);
            off ^= (off >> 3) & 0x70;
            *(uint4*)(psm + buf * PSTG + (isW ? 16384 : 0) + off) = stg[u];
        }
    };

    load_chunk(0);
    int buf = 0;
    for (int c = 0; c < PCH; c++) {
        store_chunk(buf);
        __syncthreads();
        if (c + 1 < PCH) load_chunk(c + 1);

        uint32_t stage = sb + buf * PSTG;
#pragma unroll
        for (int ks = 0; ks < 4; ks++) {
            uint32_t kx = (uint32_t)(ks << 5);
            uint32_t a[4][4], b[2][4];
#pragma unroll
            for (int mi = 0; mi < 4; mi++) ldsm_x4(a[mi], stage + (baseA[mi] ^ kx));
#pragma unroll
            for (int nj = 0; nj < 2; nj++) ldsm_x4(b[nj], stage + (baseB[nj] ^ kx));
#pragma unroll
            for (int mi = 0; mi < 4; mi++)
#pragma unroll
                for (int n8 = 0; n8 < 4; n8++)
                    mma_fp16(acc[mi][n8], a[mi], b[n8 >> 1][(n8 & 1) * 2], b[n8 >> 1][(n8 & 1) * 2 + 1]);
        }
        buf ^= 1;
    }

    const int g8 = lane >> 2, t4 = lane & 3;
    float bv[8];
#pragma unroll
    for (int n8 = 0; n8 < 4; n8++) {
        bv[n8 * 2]     = bb[n0 + n0w + n8 * 8 + t4 * 2];
        bv[n8 * 2 + 1] = bb[n0 + n0w + n8 * 8 + t4 * 2 + 1];
    }
#pragma unroll
    for (int mi = 0; mi < 4; mi++) {
        int r0 = m0 + m0w + mi * 16 + g8;
#pragma unroll
        for (int n8 = 0; n8 < 4; n8++) {
            int c0 = n0 + n0w + n8 * 8 + t4 * 2;
            __half2 v0 = __floats2half2_rn(acc[mi][n8][0] + bv[n8 * 2], acc[mi][n8][1] + bv[n8 * 2 + 1]);
            __half2 v1 = __floats2half2_rn(acc[mi][n8][2] + bv[n8 * 2], acc[mi][n8][3] + bv[n8 * 2 + 1]);
            *(__half2*)(outBase + (size_t)r0 * ROWB + c0 * 2)       = v0;
            *(__half2*)(outBase + (size_t)(r0 + 8) * ROWB + c0 * 2) = v1;
        }
    }
}

// ---------------- kernel 3: HMMA score GEMM + gate + dual max-pool ----------------
// 2 CTAs per (q,k,i); each CTA = 256 threads / 8 warps (4m x 2n), warp tile 48x48.
#define STAGES 3
#define CHUNK_B 128
#define NCHUNK 8
#define TILE_A 24576
#define STAGE_BYTES 36864
#define SM_BASE 1024
#define SMEM_TOTAL_SCORE (SM_BASE + STAGES * STAGE_BYTES)

__global__ void __launch_bounds__(256, 2)
score_mma_kernel(const float* __restrict__ g1, const float* __restrict__ bb1)
{
    extern __shared__ __align__(128) char dsm[];
    const int i = blockIdx.z, q = blockIdx.y;
    const int k = blockIdx.x >> 1;
    const int h = blockIdx.x & 1;
    const int tid = threadIdx.x;
    const int wid = tid >> 5;
    const int lane = tid & 31;
    uint32_t sb = smem_u32(dsm);

    const char* aG = (const char*)g_Qc + (size_t)((i * QN + q) * SS) * ROWB;
    const char* bG = (const char*)g_Kc + (size_t)((i * KN + k) * SS + h * 96) * ROWB;

    const int mw = wid >> 1, nw = wid & 1;     // 4 (m) x 2 (n)
    const int m0 = mw * 48;
    const int n0 = nw * 48;

    uint32_t baseA[3], baseB[3];
#pragma unroll
    for (int mi = 0; mi < 3; mi++) {
        uint32_t row = (uint32_t)(m0 + mi * 16 + (lane & 15));
        uint32_t off = row * 128 + ((lane >> 4) << 4);
        baseA[mi] = off ^ ((off >> 3) & 0x70);
    }
#pragma unroll
    for (int nt = 0; nt < 3; nt++) {
        uint32_t row = (uint32_t)(n0 + nt * 16 + (lane & 7) + ((lane >> 4) << 3));
        uint32_t off = row * 128 + (((lane >> 3) & 1) << 4);
        baseB[nt] = TILE_A + (off ^ ((off >> 3) & 0x70));
    }

    float acc[3][6][4];
#pragma unroll
    for (int mi = 0; mi < 3; mi++)
#pragma unroll
        for (int ni = 0; ni < 6; ni++)
#pragma unroll
            for (int j = 0; j < 4; j++) acc[mi][ni][j] = 0.0f;

    auto load_stage = [&](int c, int st) {
        uint32_t base = sb + SM_BASE + st * STAGE_BYTES;
#pragma unroll
        for (int l = 0; l < 9; l++) {
            int idx = tid + l * 256;            // 0..2303 16B units
            int isB = idx >= 1536;
            int j2 = isB ? idx - 1536 : idx;
            int r = j2 >> 3, g = j2 & 7;
            uint32_t off = (uint32_t)(r * 128 + g * 16);
            off ^= (off >> 3) & 0x70;
            uint32_t dst = base + (isB ? TILE_A : 0) + off;
            const void* src = (const void*)((isB ? bG : aG) + (size_t)r * ROWB + c * CHUNK_B + g * 16);
            asm volatile("cp.async.cg.shared.global [%0], [%1], 16;" :: "r"(dst), "l"(src) : "memory");
        }
        asm volatile("cp.async.commit_group;" ::: "memory");
    };

    load_stage(0, 0);
    load_stage(1, 1);

    int stc = 0, stl = 2;
    for (int it = 0; it < NCHUNK; it++) {
        if (it == NCHUNK - 1) asm volatile("cp.async.wait_group 0;" ::: "memory");
        else                  asm volatile("cp.async.wait_group 1;" ::: "memory");
        __syncthreads();
        if (it + 2 < NCHUNK) load_stage(it + 2, stl);

        uint32_t stage = sb + SM_BASE + stc * STAGE_BYTES;
#pragma unroll
        for (int ks = 0; ks < 4; ks++) {
            uint32_t kx = (uint32_t)(ks << 5);
            uint32_t a[3][4], b[3][4];
#pragma unroll
            for (int mi = 0; mi < 3; mi++) ldsm_x4(a[mi], stage + (baseA[mi] ^ kx));
#pragma unroll
            for (int nt = 0; nt < 3; nt++) ldsm_x4(b[nt], stage + (baseB[nt] ^ kx));
#pragma unroll
            for (int mi = 0; mi < 3; mi++) {
#pragma unroll
                for (int nt = 0; nt < 3; nt++) {
                    mma_fp16(acc[mi][2 * nt],     a[mi], b[nt][0], b[nt][1]);
                    mma_fp16(acc[mi][2 * nt + 1], a[mi], b[nt][2], b[nt][3]);
                }
            }
        }
        if (++stc == STAGES) stc = 0;
        if (++stl == STAGES) stl = 0;
    }

    // ---- epilogue: transposed gate + dual max-pool ----
    const float* gtb = g_GT + (size_t)i * SS * SS;
    const int g8 = lane >> 2, t4 = lane & 3;
    float rmax[6], cmax[12];
#pragma unroll
    for (int j = 0; j < 6; j++)  rmax[j] = -3.402823466e38f;
#pragma unroll
    for (int j = 0; j < 12; j++) cmax[j] = -3.402823466e38f;

#pragma unroll
    for (int mi = 0; mi < 3; mi++) {
        int r0 = m0 + mi * 16 + g8;
        int r1 = r0 + 8;
#pragma unroll
        for (int ni = 0; ni < 6; ni++) {
            int c0 = h * 96 + n0 + ni * 8 + t4 * 2;
            float2 gA = *(const float2*)(gtb + (size_t)r0 * SS + c0);
            float2 gB = *(const float2*)(gtb + (size_t)r1 * SS + c0);
            float v00 = acc[mi][ni][0] * gA.x;
            float v01 = acc[mi][ni][1] * gA.y;
            float v10 = acc[mi][ni][2] * gB.x;
            float v11 = acc[mi][ni][3] * gB.y;
            rmax[mi * 2]     = fmaxf(rmax[mi * 2],     fmaxf(v00, v01));
            rmax[mi * 2 + 1] = fmaxf(rmax[mi * 2 + 1], fmaxf(v10, v11));
            cmax[ni * 2]     = fmaxf(cmax[ni * 2],     fmaxf(v00, v10));
            cmax[ni * 2 + 1] = fmaxf(cmax[ni * 2 + 1], fmaxf(v01, v11));
        }
    }
#pragma unroll
    for (int m = 1; m <= 2; m <<= 1)
#pragma unroll
        for (int j = 0; j < 6; j++)
            rmax[j] = fmaxf(rmax[j], __shfl_xor_sync(0xffffffffu, rmax[j], m));
#pragma unroll
    for (int m = 4; m <= 16; m <<= 1)
#pragma unroll
        for (int j = 0; j < 12; j++)
            cmax[j] = fmaxf(cmax[j], __shfl_xor_sync(0xffffffffu, cmax[j], m));

    float* red1 = (float*)(dsm + SM_BASE);           // [2][192] by nw
    float* red2 = red1 + 2 * SS;                     // [4][96] by mw
    if (t4 == 0) {
#pragma unroll
        for (int j = 0; j < 6; j++)
            red1[nw * SS + m0 + (j >> 1) * 16 + g8 + (j & 1) * 8] = rmax[j];
    }
    if (g8 == 0) {
#pragma unroll
        for (int j = 0; j < 12; j++)
            red2[mw * 96 + n0 + (j >> 1) * 8 + t4 * 2 + (j & 1)] = cmax[j];
    }
    __syncthreads();

    const size_t pair = (size_t)i * NP + (size_t)q * KN + k;
    if (tid < SS) {
        float m = fmaxf(red1[tid], red1[SS + tid]);
        g_Xr[(pair * 2 + h) * SS + tid] = m;
    }
    if (tid < 96) {
        const float scale = 1.0f / sqrtf(1.0f + 1e-5f);
        float g1c = g1[i] * scale, b1v = bb1[i];
        float m = fmaxf(fmaxf(red2[tid], red2[96 + tid]),
                        fmaxf(red2[192 + tid], red2[288 + tid]));
        g_Xh[(pair * 2 + 1) * SS + h * 96 + tid] = __float2half_rn(m * g1c + b1v);
    }
}

// ---------------- kernel 3b: merge row-max halves + bn1 -> fp16 X ----------------
__global__ void merge_x_kernel(const float* __restrict__ g1, const float* __restrict__ bb1) {
    int idx = blockIdx.x * blockDim.x + threadIdx.x;
    if (idx >= NL * NP * SS) return;
    const float scale = 1.0f / sqrtf(1.0f + 1e-5f);
    int i = idx / (NP * SS);
    float g1c = g1[i] * scale, b1v = bb1[i];
    size_t pair = (size_t)(idx / SS);
    int t = idx - (int)(pair * SS);
    float rm = fmaxf(g_Xr[(pair * 2) * SS + t], g_Xr[(pair * 2 + 1) * SS + t]);
    g_Xh[(pair * 2) * SS + t] = __float2half_rn(rm * g1c + b1v);
}

// ---------------- kernel 4: HMMA mlp ----------------
#define MCH 3
#define MSTG 32768

__global__ void __launch_bounds__(256)
mlp_mma_kernel(const float* __restrict__ b2,
               const float* __restrict__ g2, const float* __restrict__ bb2,
               const float* __restrict__ w3)
{
    extern __shared__ __align__(128) char msm[];
    __shared__ float zsh[128];
    const int i = blockIdx.z;
    const int row0 = blockIdx.y * 128;
    const int col0 = blockIdx.x * 128;
    const float scale = 1.0f / sqrtf(1.0f + 1e-5f);
    const __half* W2h = g_W2h + (size_t)i * DFFN * SS;
    const __half* Xh = g_Xh + (size_t)i * NP * 2 * SS;
    const int tid = threadIdx.x, wid = tid >> 5, lane = tid & 31;
    uint32_t sb = smem_u32(msm);
    const int mw = wid >> 2, nw = wid & 3;
    const int m0w = mw * 64, n0w = nw * 32;
    if (tid < 128) zsh[tid] = 0.0f;

    uint32_t baseA[4], baseB[2];
#pragma unroll
    for (int mi = 0; mi < 4; mi++) {
        uint32_t row = (uint32_t)(m0w + mi * 16 + (lane & 15));
        uint32_t off = row * 128 + ((lane >> 4) << 4);
        baseA[mi] = off ^ ((off >> 3) & 0x70);
    }
#pragma unroll
    for (int nj = 0; nj < 2; nj++) {
        uint32_t row = (uint32_t)(n0w + nj * 16 + (lane & 7) + ((lane >> 4) << 3));
        uint32_t off = row * 128 + (((lane >> 3) & 1) << 4);
        baseB[nj] = 16384u + (off ^ ((off >> 3) & 0x70));
    }

    float acc[4][4][4];
#pragma unroll
    for (int mi = 0; mi < 4; mi++)
#pragma unroll
        for (int n8 = 0; n8 < 4; n8++)
#pragma unroll
            for (int j = 0; j < 4; j++) acc[mi][n8][j] = 0.0f;

    uint4 stg[8];
    auto load_chunk = [&](int c) {
        const int kk0 = c * 64;
#pragma unroll
        for (int u = 0; u < 8; u++) {
            int idx = tid + u * 256;
            int isW = idx >= 1024;
            int j = idx & 1023;
            int r = j >> 3, g = j & 7;
            const __half* src = isW ? (W2h + (size_t)(col0 + r) * SS + kk0 + g * 8)
                                    : (Xh  + (size_t)(row0 + r) * SS + kk0 + g * 8);
            stg[u] = *(const uint4*)src;
        }
    };
    auto store_chunk = [&](int buf) {
#pragma unroll
        for (int u = 0; u < 8; u++) {
            int idx = tid + u * 256;
            int isW = idx >= 1024;
            int j = idx & 1023;
            int r = j >> 3, g = j & 7;
            uint32_t off = (uint32_t)(r * 128 + g * 16);
            off ^= (off >> 3) & 0x70;
            *(uint4*)(msm + buf * MSTG + (isW ? 16384 : 0) + off) = stg[u];
        }
    };

    load_chunk(0);
    int buf = 0;
    for (int c = 0; c < MCH; c++) {
        store_chunk(buf);
        __syncthreads();
        if (c + 1 < MCH) load_chunk(c + 1);

        uint32_t stage = sb + buf * MSTG;
#pragma unroll
        for (int ks = 0; ks < 4; ks++) {
            uint32_t kx = (uint32_t)(ks << 5);
            uint32_t a[4][4], b[2][4];
#pragma unroll
            for (int mi = 0; mi < 4; mi++) ldsm_x4(a[mi], stage + (baseA[mi] ^ kx));
#pragma unroll
            for (int nj = 0; nj < 2; nj++) ldsm_x4(b[nj], stage + (baseB[nj] ^ kx));
#pragma unroll
            for (int mi = 0; mi < 4; mi++)
#pragma unroll
                for (int n8 = 0; n8 < 4; n8++)
                    mma_fp16(acc[mi][n8], a[mi], b[n8 >> 1][(n8 & 1) * 2], b[n8 >> 1][(n8 & 1) * 2 + 1]);
        }
        buf ^= 1;
    }

    const int g8 = lane >> 2, t4 = lane & 3;
    float b2v[8], g2v[8], bb2v[8], w3v[8];
#pragma unroll
    for (int n8 = 0; n8 < 4; n8++) {
        int c0 = col0 + n0w + n8 * 8 + t4 * 2;
        b2v[n8*2]   = __ldg(b2  + (size_t)i * DFFN + c0);
        b2v[n8*2+1] = __ldg(b2  + (size_t)i * DFFN + c0 + 1);
        g2v[n8*2]   = __ldg(g2  + (size_t)i * DFFN + c0);
        g2v[n8*2+1] = __ldg(g2  + (size_t)i * DFFN + c0 + 1);
        bb2v[n8*2]   = __ldg(bb2 + (size_t)i * DFFN + c0);
        bb2v[n8*2+1] = __ldg(bb2 + (size_t)i * DFFN + c0 + 1);
        w3v[n8*2]   = __ldg(w3  + (size_t)i * DFFN + c0);
        w3v[n8*2+1] = __ldg(w3  + (size_t)i * DFFN + c0 + 1);
    }
    __syncthreads();

#pragma unroll
    for (int mi = 0; mi < 4; mi++) {
        float zp0 = 0.0f, zp1 = 0.0f;
#pragma unroll
        for (int n8 = 0; n8 < 4; n8++) {
#pragma unroll
            for (int e = 0; e < 2; e++) {
                float y0 = acc[mi][n8][e]     + b2v[n8*2+e];
                float y1 = acc[mi][n8][2 + e] + b2v[n8*2+e];
                float yb0 = y0 * (g2v[n8*2+e] * scale) + bb2v[n8*2+e];
                float yb1 = y1 * (g2v[n8*2+e] * scale) + bb2v[n8*2+e];
                if (yb0 > 0.0f) zp0 += yb0 * w3v[n8*2+e];
                if (yb1 > 0.0f) zp1 += yb1 * w3v[n8*2+e];
            }
        }
        zp0 += __shfl_xor_sync(0xffffffffu, zp0, 1);
        zp0 += __shfl_xor_sync(0xffffffffu, zp0, 2);
        zp1 += __shfl_xor_sync(0xffffffffu, zp1, 1);
        zp1 += __shfl_xor_sync(0xffffffffu, zp1, 2);
        if (t4 == 0) {
            atomicAdd(&zsh[m0w + mi * 16 + g8], zp0);
            atomicAdd(&zsh[m0w + mi * 16 + g8 + 8], zp1);
        }
    }
    __syncthreads();
    if (tid < 128) atomicAdd(&g_Z[(size_t)i * NP * 2 + row0 + tid], zsh[tid]);
}

// ---------------- kernel 5: final ----------------
__global__ void final_kernel(const float* __restrict__ fc3_b,
                             const float* __restrict__ bn3_g, const float* __restrict__ bn3_b,
                             const float* __restrict__ norm_g, const float* __restrict__ norm_b,
                             float* __restrict__ out)
{
    int p = blockIdx.x * blockDim.x + threadIdx.x;
    if (p >= NP) return;
    const float scale = 1.0f / sqrtf(1.0f + 1e-5f);
    float acc = 0.0f;
#pragma unroll
    for (int i = 0; i < NL; i++) {
        float u = g_Z[i * NP * 2 + 2 * p] + g_Z[i * NP * 2 + 2 * p + 1] + 2.0f * fc3_b[i];
        acc += u * (bn3_g[i] * scale) + bn3_b[i];
    }
    out[p] = acc * (norm_g[0] * scale) + norm_b[0];
}

// ---------------- launch ----------------
extern "C" void kernel_launch(void* const* d_in, const int* in_sizes, int n_in,
                              void* d_out, int out_size)
{
    (void)in_sizes; (void)n_in; (void)out_size;
    const float* memory_  = (const float*)d_in[0];
    const float* features = (const float*)d_in[1];
    const float* fc1_w  = (const float*)d_in[2];
    const float* fc1_b  = (const float*)d_in[3];
    const float* se     = (const float*)d_in[4];
    const float* bn1_g  = (const float*)d_in[5];
    const float* bn1_b  = (const float*)d_in[6];
    const float* fc2_w  = (const float*)d_in[7];
    const float* fc2_b  = (const float*)d_in[8];
    const float* bn2_g  = (const float*)d_in[9];
    const float* bn2_b  = (const float*)d_in[10];
    const float* fc3_w  = (const float*)d_in[11];
    const float* fc3_b  = (const float*)d_in[12];
    const float* bn3_g  = (const float*)d_in[13];
    const float* bn3_b  = (const float*)d_in[14];
    const float* norm_g = (const float*)d_in[15];
    const float* norm_b = (const float*)d_in[16];
    float* out = (float*)d_out;

    cudaFuncSetAttribute(score_mma_kernel,
                         cudaFuncAttributeMaxDynamicSharedMemorySize, SMEM_TOTAL_SCORE);
    cudaFuncSetAttribute(proj_mma_kernel,
                         cudaFuncAttributeMaxDynamicSharedMemorySize, 2 * PSTG);
    cudaFuncSetAttribute(mlp_mma_kernel,
                         cudaFuncAttributeMaxDynamicSharedMemorySize, 2 * MSTG);

    prep_kernel<<<(PREP_N + 255) / 256, 256>>>(memory_, features, fc1_w, fc2_w, se);

    proj_mma_kernel<<<dim3(DH / 128, (QN * SS) / 128, 2 * NL), 256, 2 * PSTG>>>(fc1_b);

    score_mma_kernel<<<dim3(KN * 2, QN, NL), 256, SMEM_TOTAL_SCORE>>>(bn1_g, bn1_b);

    merge_x_kernel<<<(NL * NP * SS + 255) / 256, 256>>>(bn1_g, bn1_b);

    mlp_mma_kernel<<<dim3(DFFN / 128, (2 * NP) / 128, NL), 256, 2 * MSTG>>>(
        fc2_b, bn2_g, bn2_b, fc3_w);

    final_kernel<<<(NP + 255) / 256, 256>>>(fc3_b, bn3_g, bn3_b, norm_g, norm_b, out);
}

// round 16
// speedup vs baseline: 1.0188x; 1.0188x over previous
#include <cuda_runtime.h>
#include <cuda_bf16.h>
#include <cuda_fp16.h>
#include <math.h>
#include <stdint.h>

typedef unsigned long long ull;

#define QN 48
#define KN 48
#define SS 192
#define DH 512
#define NL 3
#define DFFN 2048
#define NP (QN*KN)   /* 2304 */
#define KC 512
#define ROWB 1024    /* bytes per row = KC * 2 */

#define AELEM (NL*QN*SS*DH)
#define CA_U4 (AELEM/8)
#define W1_U4 (NL*DH*DH/8)
#define W2_U4 (NL*DFFN*SS/8)
#define PREP_N (2*CA_U4 + W1_U4 + W2_U4)
#define MLP_BLOCKS ((DFFN/128) * ((2*NP)/128) * NL)   /* 16*36*3 = 1728 */

// ---------------- scratch (device globals) ----------------
__device__ uint4  g_Qc[(size_t)NL*QN*SS*ROWB/16];
__device__ uint4  g_Kc[(size_t)NL*KN*SS*ROWB/16];
__device__ __align__(16) __half g_Mh[AELEM];
__device__ __align__(16) __half g_Fh[AELEM];
__device__ __align__(16) __half g_W1h[NL*DH*DH];
__device__ __align__(16) __half g_W2h[NL*DFFN*SS];
__device__ __align__(16) float g_GT[NL * SS * SS];
__device__ float  g_Xr[(size_t)NL * NP * 2 * SS];
__device__ __align__(16) __half g_Xh[(size_t)NL * NP * 2 * SS];
__device__ float  g_Z [NL * NP * 2];
__device__ unsigned int g_tick[NL * NP];
__device__ unsigned int g_mdone;

__device__ __forceinline__ uint32_t smem_u32(const void* p) {
    uint32_t a;
    asm("{ .reg .u64 t; cvta.to.shared.u64 t, %1; cvt.u32.u64 %0, t; }" : "=r"(a) : "l"(p));
    return a;
}

// ---------------- mma / ldmatrix wrappers ----------------
__device__ __forceinline__ void mma_fp16(float* d, const uint32_t* a, uint32_t b0, uint32_t b1) {
    asm volatile("mma.sync.aligned.m16n8k16.row.col.f32.f16.f16.f32 "
                 "{%0,%1,%2,%3}, {%4,%5,%6,%7}, {%8,%9}, {%0,%1,%2,%3};"
                 : "+f"(d[0]), "+f"(d[1]), "+f"(d[2]), "+f"(d[3])
                 : "r"(a[0]), "r"(a[1]), "r"(a[2]), "r"(a[3]), "r"(b0), "r"(b1));
}
__device__ __forceinline__ void ldsm_x4(uint32_t* r, uint32_t addr) {
    asm volatile("ldmatrix.sync.aligned.m8n8.x4.shared.b16 {%0,%1,%2,%3}, [%4];"
                 : "=r"(r[0]), "=r"(r[1]), "=r"(r[2]), "=r"(r[3]) : "r"(addr));
}

// ---------------- kernel 1: prep ----------------
__device__ __forceinline__ void cvt8(const float* __restrict__ src, __half* dst, int u) {
    float4 f0 = ((const float4*)src)[u * 2];
    float4 f1 = ((const float4*)src)[u * 2 + 1];
    __half2 a0 = __floats2half2_rn(f0.x, f0.y);
    __half2 a1 = __floats2half2_rn(f0.z, f0.w);
    __half2 a2 = __floats2half2_rn(f1.x, f1.y);
    __half2 a3 = __floats2half2_rn(f1.z, f1.w);
    uint4 v;
    v.x = *reinterpret_cast<uint32_t*>(&a0);
    v.y = *reinterpret_cast<uint32_t*>(&a1);
    v.z = *reinterpret_cast<uint32_t*>(&a2);
    v.w = *reinterpret_cast<uint32_t*>(&a3);
    ((uint4*)dst)[u] = v;
}

__global__ void prep_kernel(const float* __restrict__ mem, const float* __restrict__ feat,
                            const float* __restrict__ w1, const float* __restrict__ w2,
                            const float* __restrict__ se)
{
    int idx = blockIdx.x * blockDim.x + threadIdx.x;
    if (idx < CA_U4)                       cvt8(mem,  g_Mh,  idx);
    else if (idx < 2*CA_U4)                cvt8(feat, g_Fh,  idx - CA_U4);
    else if (idx < 2*CA_U4 + W1_U4)        cvt8(w1,   g_W1h, idx - 2*CA_U4);
    else if (idx < PREP_N)                 cvt8(w2,   g_W2h, idx - 2*CA_U4 - W1_U4);
    if (idx < NL * SS * SS) {
        int i = idx / (SS * SS);
        int rem = idx - i * SS * SS;
        int t = rem / SS, s = rem - t * SS;
        g_GT[idx] = 1.0f / (1.0f + expf(-se[i * SS * SS + s * SS + t]));
    }
    if (idx < NL * NP * 2) g_Z[idx] = 0.0f;
    if (idx < NL * NP)     g_tick[idx] = 0u;
    if (idx == 0)          g_mdone = 0u;
}

// ---------------- kernel 2: projection GEMM (HMMA, fp16 in, both dsts) ----------------
#define PCH 8
#define PSTG 32768

__global__ void __launch_bounds__(256)
proj_mma_kernel(const float* __restrict__ bias)
{
    extern __shared__ __align__(128) char psm[];
    const int z = blockIdx.z;
    const int i = (z < NL) ? z : z - NL;
    const int dst = (z >= NL);
    const __half* Ah = (dst ? g_Fh : g_Mh) + i * DH;
    const __half* Wh = g_W1h + (size_t)i * DH * DH;
    const float* bb = bias + i * DH;
    const int LDA = NL * DH;
    char* outBase = (char*)(dst ? g_Kc : g_Qc) + (size_t)(i * QN * SS) * ROWB;
    const int m0 = blockIdx.y * 128, n0 = blockIdx.x * 128;
    const int tid = threadIdx.x, wid = tid >> 5, lane = tid & 31;
    uint32_t sb = smem_u32(psm);
    const int mw = wid >> 2, nw = wid & 3;
    const int m0w = mw * 64, n0w = nw * 32;

    uint32_t baseA[4], baseB[2];
#pragma unroll
    for (int mi = 0; mi < 4; mi++) {
        uint32_t row = (uint32_t)(m0w + mi * 16 + (lane & 15));
        uint32_t off = row * 128 + ((lane >> 4) << 4);
        baseA[mi] = off ^ ((off >> 3) & 0x70);
    }
#pragma unroll
    for (int nj = 0; nj < 2; nj++) {
        uint32_t row = (uint32_t)(n0w + nj * 16 + (lane & 7) + ((lane >> 4) << 3));
        uint32_t off = row * 128 + (((lane >> 3) & 1) << 4);
        baseB[nj] = 16384u + (off ^ ((off >> 3) & 0x70));
    }

    float acc[4][4][4];
#pragma unroll
    for (int mi = 0; mi < 4; mi++)
#pragma unroll
        for (int n8 = 0; n8 < 4; n8++)
#pragma unroll
            for (int j = 0; j < 4; j++) acc[mi][n8][j] = 0.0f;

    uint4 stg[8];
    auto load_chunk = [&](int c) {
        const int co0 = c * 64;
#pragma unroll
        for (int u = 0; u < 8; u++) {
            int idx = tid + u * 256;
            int isW = idx >= 1024;
            int j = idx & 1023;
            int r = j >> 3, g = j & 7;
            const __half* src = isW ? (Wh + (size_t)(n0 + r) * DH  + co0 + g * 8)
                                    : (Ah + (size_t)(m0 + r) * LDA + co0 + g * 8);
            stg[u] = *(const uint4*)src;
        }
    };
    auto store_chunk = [&](int buf) {
#pragma unroll
        for (int u = 0; u < 8; u++) {
            int idx = tid + u * 256;
            int isW = idx >= 1024;
            int j = idx & 1023;
            int r = j >> 3, g = j & 7;
            uint32_t off = (uint32_t)(r * 128 + g * 16);
            off ^= (off >> 3) & 0x70;
            *(uint4*)(psm + buf * PSTG + (isW ? 16384 : 0) + off) = stg[u];
        }
    };

    load_chunk(0);
    int buf = 0;
    for (int c = 0; c < PCH; c++) {
        store_chunk(buf);
        __syncthreads();
        if (c + 1 < PCH) load_chunk(c + 1);

        uint32_t stage = sb + buf * PSTG;
#pragma unroll
        for (int ks = 0; ks < 4; ks++) {
            uint32_t kx = (uint32_t)(ks << 5);
            uint32_t a[4][4], b[2][4];
#pragma unroll
            for (int mi = 0; mi < 4; mi++) ldsm_x4(a[mi], stage + (baseA[mi] ^ kx));
#pragma unroll
            for (int nj = 0; nj < 2; nj++) ldsm_x4(b[nj], stage + (baseB[nj] ^ kx));
#pragma unroll
            for (int mi = 0; mi < 4; mi++)
#pragma unroll
                for (int n8 = 0; n8 < 4; n8++)
                    mma_fp16(acc[mi][n8], a[mi], b[n8 >> 1][(n8 & 1) * 2], b[n8 >> 1][(n8 & 1) * 2 + 1]);
        }
        buf ^= 1;
    }

    const int g8 = lane >> 2, t4 = lane & 3;
    float bv[8];
#pragma unroll
    for (int n8 = 0; n8 < 4; n8++) {
        bv[n8 * 2]     = bb[n0 + n0w + n8 * 8 + t4 * 2];
        bv[n8 * 2 + 1] = bb[n0 + n0w + n8 * 8 + t4 * 2 + 1];
    }
#pragma unroll
    for (int mi = 0; mi < 4; mi++) {
        int r0 = m0 + m0w + mi * 16 + g8;
#pragma unroll
        for (int n8 = 0; n8 < 4; n8++) {
            int c0 = n0 + n0w + n8 * 8 + t4 * 2;
            __half2 v0 = __floats2half2_rn(acc[mi][n8][0] + bv[n8 * 2], acc[mi][n8][1] + bv[n8 * 2 + 1]);
            __half2 v1 = __floats2half2_rn(acc[mi][n8][2] + bv[n8 * 2], acc[mi][n8][3] + bv[n8 * 2 + 1]);
            *(__half2*)(outBase + (size_t)r0 * ROWB + c0 * 2)       = v0;
            *(__half2*)(outBase + (size_t)(r0 + 8) * ROWB + c0 * 2) = v1;
        }
    }
}

// ---------------- kernel 3: HMMA score GEMM + gate + dual max-pool + fused merge ----------------
// 2 CTAs per (q,k,i): each 192 threads / 6 warps computes 192 x 96 (N split).
#define STAGES 3
#define CHUNK_B 128
#define NCHUNK 8
#define TILE_A 24576
#define STAGE_BYTES 36864
#define SM_BASE 1024
#define SMEM_TOTAL_SCORE (SM_BASE + STAGES * STAGE_BYTES)

__global__ void __launch_bounds__(192, 2)
score_mma_kernel(const float* __restrict__ g1, const float* __restrict__ bb1)
{
    extern __shared__ __align__(128) char dsm[];
    __shared__ unsigned int sflag;
    const int i = blockIdx.z, q = blockIdx.y;
    const int k = blockIdx.x >> 1;
    const int h = blockIdx.x & 1;
    const int tid = threadIdx.x;
    const int wid = tid >> 5;
    const int lane = tid & 31;
    uint32_t sb = smem_u32(dsm);

    const char* aG = (const char*)g_Qc + (size_t)((i * QN + q) * SS) * ROWB;
    const char* bG = (const char*)g_Kc + (size_t)((i * KN + k) * SS + h * 96) * ROWB;

    const int mw = wid >> 1, nw = wid & 1;
    const int m0 = mw * 64;
    const int n0 = nw * 48;

    uint32_t baseA[4], baseB[3];
#pragma unroll
    for (int mi = 0; mi < 4; mi++) {
        uint32_t row = (uint32_t)(m0 + mi * 16 + (lane & 15));
        uint32_t off = row * 128 + ((lane >> 4) << 4);
        baseA[mi] = off ^ ((off >> 3) & 0x70);
    }
#pragma unroll
    for (int nt = 0; nt < 3; nt++) {
        uint32_t row = (uint32_t)(n0 + nt * 16 + (lane & 7) + ((lane >> 4) << 3));
        uint32_t off = row * 128 + (((lane >> 3) & 1) << 4);
        baseB[nt] = TILE_A + (off ^ ((off >> 3) & 0x70));
    }

    float acc[4][6][4];
#pragma unroll
    for (int mi = 0; mi < 4; mi++)
#pragma unroll
        for (int ni = 0; ni < 6; ni++)
#pragma unroll
            for (int j = 0; j < 4; j++) acc[mi][ni][j] = 0.0f;

    auto load_stage = [&](int c, int st) {
        uint32_t base = sb + SM_BASE + st * STAGE_BYTES;
#pragma unroll
        for (int l = 0; l < 12; l++) {
            int idx = tid + l * 192;
            int isB = idx >= 1536;
            int j2 = isB ? idx - 1536 : idx;
            int r = j2 >> 3, g = j2 & 7;
            uint32_t off = (uint32_t)(r * 128 + g * 16);
            off ^= (off >> 3) & 0x70;
            uint32_t dst = base + (isB ? TILE_A : 0) + off;
            const void* src = (const void*)((isB ? bG : aG) + (size_t)r * ROWB + c * CHUNK_B + g * 16);
            asm volatile("cp.async.cg.shared.global [%0], [%1], 16;" :: "r"(dst), "l"(src) : "memory");
        }
        asm volatile("cp.async.commit_group;" ::: "memory");
    };

    load_stage(0, 0);
    load_stage(1, 1);

    int stc = 0, stl = 2;
    for (int it = 0; it < NCHUNK; it++) {
        if (it == NCHUNK - 1) asm volatile("cp.async.wait_group 0;" ::: "memory");
        else                  asm volatile("cp.async.wait_group 1;" ::: "memory");
        __syncthreads();
        if (it + 2 < NCHUNK) load_stage(it + 2, stl);

        uint32_t stage = sb + SM_BASE + stc * STAGE_BYTES;
#pragma unroll
        for (int ks = 0; ks < 4; ks++) {
            uint32_t kx = (uint32_t)(ks << 5);
            uint32_t a[4][4], b[3][4];
#pragma unroll
            for (int mi = 0; mi < 4; mi++) ldsm_x4(a[mi], stage + (baseA[mi] ^ kx));
#pragma unroll
            for (int nt = 0; nt < 3; nt++) ldsm_x4(b[nt], stage + (baseB[nt] ^ kx));
#pragma unroll
            for (int mi = 0; mi < 4; mi++) {
#pragma unroll
                for (int nt = 0; nt < 3; nt++) {
                    mma_fp16(acc[mi][2 * nt],     a[mi], b[nt][0], b[nt][1]);
                    mma_fp16(acc[mi][2 * nt + 1], a[mi], b[nt][2], b[nt][3]);
                }
            }
        }
        if (++stc == STAGES) stc = 0;
        if (++stl == STAGES) stl = 0;
    }

    // ---- epilogue: transposed gate + dual max-pool ----
    const float* gtb = g_GT + (size_t)i * SS * SS;
    const int g8 = lane >> 2, t4 = lane & 3;
    float rmax[8], cmax[12];
#pragma unroll
    for (int j = 0; j < 8; j++)  rmax[j] = -3.402823466e38f;
#pragma unroll
    for (int j = 0; j < 12; j++) cmax[j] = -3.402823466e38f;

#pragma unroll
    for (int mi = 0; mi < 4; mi++) {
        int r0 = m0 + mi * 16 + g8;
        int r1 = r0 + 8;
#pragma unroll
        for (int ni = 0; ni < 6; ni++) {
            int c0 = h * 96 + n0 + ni * 8 + t4 * 2;
            float2 gA = *(const float2*)(gtb + (size_t)r0 * SS + c0);
            float2 gB = *(const float2*)(gtb + (size_t)r1 * SS + c0);
            float v00 = acc[mi][ni][0] * gA.x;
            float v01 = acc[mi][ni][1] * gA.y;
            float v10 = acc[mi][ni][2] * gB.x;
            float v11 = acc[mi][ni][3] * gB.y;
            rmax[mi * 2]     = fmaxf(rmax[mi * 2],     fmaxf(v00, v01));
            rmax[mi * 2 + 1] = fmaxf(rmax[mi * 2 + 1], fmaxf(v10, v11));
            cmax[ni * 2]     = fmaxf(cmax[ni * 2],     fmaxf(v00, v10));
            cmax[ni * 2 + 1] = fmaxf(cmax[ni * 2 + 1], fmaxf(v01, v11));
        }
    }
#pragma unroll
    for (int m = 1; m <= 2; m <<= 1)
#pragma unroll
        for (int j = 0; j < 8; j++)
            rmax[j] = fmaxf(rmax[j], __shfl_xor_sync(0xffffffffu, rmax[j], m));
#pragma unroll
    for (int m = 4; m <= 16; m <<= 1)
#pragma unroll
        for (int j = 0; j < 12; j++)
            cmax[j] = fmaxf(cmax[j], __shfl_xor_sync(0xffffffffu, cmax[j], m));

    float* red1 = (float*)(dsm + SM_BASE);
    float* red2 = red1 + 2 * SS;
    if (t4 == 0) {
#pragma unroll
        for (int j = 0; j < 8; j++)
            red1[nw * SS + m0 + (j >> 1) * 16 + g8 + (j & 1) * 8] = rmax[j];
    }
    if (g8 == 0) {
#pragma unroll
        for (int j = 0; j < 12; j++)
            red2[mw * 96 + n0 + (j >> 1) * 8 + t4 * 2 + (j & 1)] = cmax[j];
    }
    __syncthreads();

    const float scale = 1.0f / sqrtf(1.0f + 1e-5f);
    const float g1c = g1[i] * scale, b1v = bb1[i];
    const size_t pair = (size_t)i * NP + (size_t)q * KN + k;
    {
        float m = fmaxf(red1[tid], red1[SS + tid]);
        g_Xr[(pair * 2 + h) * SS + tid] = m;          // partial row-max (this half)
    }
    if (tid < 96) {
        float m = fmaxf(fmaxf(red2[tid], red2[96 + tid]), red2[192 + tid]);
        g_Xh[(pair * 2 + 1) * SS + h * 96 + tid] = __float2half_rn(m * g1c + b1v);
    }
    // ---- fused merge: second CTA of the pair combines row-max halves ----
    __syncthreads();
    if (tid == 0) {
        __threadfence();
        sflag = atomicAdd(&g_tick[pair], 1u);
    }
    __syncthreads();
    if (sflag == 1u) {
        __threadfence();
        float rm = fmaxf(g_Xr[(pair * 2) * SS + tid], g_Xr[(pair * 2 + 1) * SS + tid]);
        g_Xh[(pair * 2) * SS + tid] = __float2half_rn(rm * g1c + b1v);
    }
}

// ---------------- kernel 4: HMMA mlp + fused final ----------------
#define MCH 3
#define MSTG 32768

__global__ void __launch_bounds__(256)
mlp_mma_kernel(const float* __restrict__ b2,
               const float* __restrict__ g2, const float* __restrict__ bb2,
               const float* __restrict__ w3,
               const float* __restrict__ fc3_b,
               const float* __restrict__ bn3_g, const float* __restrict__ bn3_b,
               const float* __restrict__ norm_g, const float* __restrict__ norm_b,
               float* __restrict__ out)
{
    extern __shared__ __align__(128) char msm[];
    __shared__ float zsh[128];
    __shared__ unsigned int mflag;
    const int i = blockIdx.z;
    const int row0 = blockIdx.y * 128;
    const int col0 = blockIdx.x * 128;
    const float scale = 1.0f / sqrtf(1.0f + 1e-5f);
    const __half* W2h = g_W2h + (size_t)i * DFFN * SS;
    const __half* Xh = g_Xh + (size_t)i * NP * 2 * SS;
    const int tid = threadIdx.x, wid = tid >> 5, lane = tid & 31;
    uint32_t sb = smem_u32(msm);
    const int mw = wid >> 2, nw = wid & 3;
    const int m0w = mw * 64, n0w = nw * 32;
    if (tid < 128) zsh[tid] = 0.0f;

    uint32_t baseA[4], baseB[2];
#pragma unroll
    for (int mi = 0; mi < 4; mi++) {
        uint32_t row = (uint32_t)(m0w + mi * 16 + (lane & 15));
        uint32_t off = row * 128 + ((lane >> 4) << 4);
        baseA[mi] = off ^ ((off >> 3) & 0x70);
    }
#pragma unroll
    for (int nj = 0; nj < 2; nj++) {
        uint32_t row = (uint32_t)(n0w + nj * 16 + (lane & 7) + ((lane >> 4) << 3));
        uint32_t off = row * 128 + (((lane >> 3) & 1) << 4);
        baseB[nj] = 16384u + (off ^ ((off >> 3) & 0x70));
    }

    float acc[4][4][4];
#pragma unroll
    for (int mi = 0; mi < 4; mi++)
#pragma unroll
        for (int n8 = 0; n8 < 4; n8++)
#pragma unroll
            for (int j = 0; j < 4; j++) acc[mi][n8][j] = 0.0f;

    uint4 stg[8];
    auto load_chunk = [&](int c) {
        const int kk0 = c * 64;
#pragma unroll
        for (int u = 0; u < 8; u++) {
            int idx = tid + u * 256;
            int isW = idx >= 1024;
            int j = idx & 1023;
            int r = j >> 3, g = j & 7;
            const __half* src = isW ? (W2h + (size_t)(col0 + r) * SS + kk0 + g * 8)
                                    : (Xh  + (size_t)(row0 + r) * SS + kk0 + g * 8);
            stg[u] = *(const uint4*)src;
        }
    };
    auto store_chunk = [&](int buf) {
#pragma unroll
        for (int u = 0; u < 8; u++) {
            int idx = tid + u * 256;
            int isW = idx >= 1024;
            int j = idx & 1023;
            int r = j >> 3, g = j & 7;
            uint32_t off = (uint32_t)(r * 128 + g * 16);
            off ^= (off >> 3) & 0x70;
            *(uint4*)(msm + buf * MSTG + (isW ? 16384 : 0) + off) = stg[u];
        }
    };

    load_chunk(0);
    int buf = 0;
    for (int c = 0; c < MCH; c++) {
        store_chunk(buf);
        __syncthreads();
        if (c + 1 < MCH) load_chunk(c + 1);

        uint32_t stage = sb + buf * MSTG;
#pragma unroll
        for (int ks = 0; ks < 4; ks++) {
            uint32_t kx = (uint32_t)(ks << 5);
            uint32_t a[4][4], b[2][4];
#pragma unroll
            for (int mi = 0; mi < 4; mi++) ldsm_x4(a[mi], stage + (baseA[mi] ^ kx));
#pragma unroll
            for (int nj = 0; nj < 2; nj++) ldsm_x4(b[nj], stage + (baseB[nj] ^ kx));
#pragma unroll
            for (int mi = 0; mi < 4; mi++)
#pragma unroll
                for (int n8 = 0; n8 < 4; n8++)
                    mma_fp16(acc[mi][n8], a[mi], b[n8 >> 1][(n8 & 1) * 2], b[n8 >> 1][(n8 & 1) * 2 + 1]);
        }
        buf ^= 1;
    }

    const int g8 = lane >> 2, t4 = lane & 3;
    float b2v[8], g2v[8], bb2v[8], w3v[8];
#pragma unroll
    for (int n8 = 0; n8 < 4; n8++) {
        int c0 = col0 + n0w + n8 * 8 + t4 * 2;
        b2v[n8*2]   = __ldg(b2  + (size_t)i * DFFN + c0);
        b2v[n8*2+1] = __ldg(b2  + (size_t)i * DFFN + c0 + 1);
        g2v[n8*2]   = __ldg(g2  + (size_t)i * DFFN + c0);
        g2v[n8*2+1] = __ldg(g2  + (size_t)i * DFFN + c0 + 1);
        bb2v[n8*2]   = __ldg(bb2 + (size_t)i * DFFN + c0);
        bb2v[n8*2+1] = __ldg(bb2 + (size_t)i * DFFN + c0 + 1);
        w3v[n8*2]   = __ldg(w3  + (size_t)i * DFFN + c0);
        w3v[n8*2+1] = __ldg(w3  + (size_t)i * DFFN + c0 + 1);
    }
    __syncthreads();

#pragma unroll
    for (int mi = 0; mi < 4; mi++) {
        float zp0 = 0.0f, zp1 = 0.0f;
#pragma unroll
        for (int n8 = 0; n8 < 4; n8++) {
#pragma unroll
            for (int e = 0; e < 2; e++) {
                float y0 = acc[mi][n8][e]     + b2v[n8*2+e];
                float y1 = acc[mi][n8][2 + e] + b2v[n8*2+e];
                float yb0 = y0 * (g2v[n8*2+e] * scale) + bb2v[n8*2+e];
                float yb1 = y1 * (g2v[n8*2+e] * scale) + bb2v[n8*2+e];
                if (yb0 > 0.0f) zp0 += yb0 * w3v[n8*2+e];
                if (yb1 > 0.0f) zp1 += yb1 * w3v[n8*2+e];
            }
        }
        zp0 += __shfl_xor_sync(0xffffffffu, zp0, 1);
        zp0 += __shfl_xor_sync(0xffffffffu, zp0, 2);
        zp1 += __shfl_xor_sync(0xffffffffu, zp1, 1);
        zp1 += __shfl_xor_sync(0xffffffffu, zp1, 2);
        if (t4 == 0) {
            atomicAdd(&zsh[m0w + mi * 16 + g8], zp0);
            atomicAdd(&zsh[m0w + mi * 16 + g8 + 8], zp1);
        }
    }
    __syncthreads();
    if (tid < 128) atomicAdd(&g_Z[(size_t)i * NP * 2 + row0 + tid], zsh[tid]);

    // ---- fused final: last block computes the output ----
    __syncthreads();
    if (tid == 0) {
        __threadfence();
        mflag = atomicAdd(&g_mdone, 1u);
    }
    __syncthreads();
    if (mflag == MLP_BLOCKS - 1) {
        __threadfence();
        for (int p = tid; p < NP; p += 256) {
            float accv = 0.0f;
#pragma unroll
            for (int ii = 0; ii < NL; ii++) {
                float u = g_Z[ii * NP * 2 + 2 * p] + g_Z[ii * NP * 2 + 2 * p + 1] + 2.0f * fc3_b[ii];
                accv += u * (bn3_g[ii] * scale) + bn3_b[ii];
            }
            out[p] = accv * (norm_g[0] * scale) + norm_b[0];
        }
    }
}

// ---------------- launch ----------------
extern "C" void kernel_launch(void* const* d_in, const int* in_sizes, int n_in,
                              void* d_out, int out_size)
{
    (void)in_sizes; (void)n_in; (void)out_size;
    const float* memory_  = (const float*)d_in[0];
    const float* features = (const float*)d_in[1];
    const float* fc1_w  = (const float*)d_in[2];
    const float* fc1_b  = (const float*)d_in[3];
    const float* se     = (const float*)d_in[4];
    const float* bn1_g  = (const float*)d_in[5];
    const float* bn1_b  = (const float*)d_in[6];
    const float* fc2_w  = (const float*)d_in[7];
    const float* fc2_b  = (const float*)d_in[8];
    const float* bn2_g  = (const float*)d_in[9];
    const float* bn2_b  = (const float*)d_in[10];
    const float* fc3_w  = (const float*)d_in[11];
    const float* fc3_b  = (const float*)d_in[12];
    const float* bn3_g  = (const float*)d_in[13];
    const float* bn3_b  = (const float*)d_in[14];
    const float* norm_g = (const float*)d_in[15];
    const float* norm_b = (const float*)d_in[16];
    float* out = (float*)d_out;

    cudaFuncSetAttribute(score_mma_kernel,
                         cudaFuncAttributeMaxDynamicSharedMemorySize, SMEM_TOTAL_SCORE);
    cudaFuncSetAttribute(proj_mma_kernel,
                         cudaFuncAttributeMaxDynamicSharedMemorySize, 2 * PSTG);
    cudaFuncSetAttribute(mlp_mma_kernel,
                         cudaFuncAttributeMaxDynamicSharedMemorySize, 2 * MSTG);

    prep_kernel<<<(PREP_N + 255) / 256, 256>>>(memory_, features, fc1_w, fc2_w, se);

    proj_mma_kernel<<<dim3(DH / 128, (QN * SS) / 128, 2 * NL), 256, 2 * PSTG>>>(fc1_b);

    score_mma_kernel<<<dim3(KN * 2, QN, NL), 192, SMEM_TOTAL_SCORE>>>(bn1_g, bn1_b);

    mlp_mma_kernel<<<dim3(DFFN / 128, (2 * NP) / 128, NL), 256, 2 * MSTG>>>(
        fc2_b, bn2_g, bn2_b, fc3_w, fc3_b, bn3_g, bn3_b, norm_g, norm_b, out);
}

// round 17
// speedup vs baseline: 1.0602x; 1.0406x over previous
#include <cuda_runtime.h>
#include <cuda_bf16.h>
#include <cuda_fp16.h>
#include <math.h>
#include <stdint.h>

typedef unsigned long long ull;

#define QN 48
#define KN 48
#define SS 192
#define DH 512
#define NL 3
#define DFFN 2048
#define NP (QN*KN)   /* 2304 */
#define KC 512
#define ROWB 1024    /* bytes per row = KC * 2 */

#define AELEM (NL*QN*SS*DH)
#define CA_U4 (AELEM/8)
#define W1_U4 (NL*DH*DH/8)
#define W2_U4 (NL*DFFN*SS/8)
#define PREP_N (2*CA_U4 + W1_U4 + W2_U4)
#define MLP_BLOCKS ((DFFN/128) * ((2*NP)/128) * NL)   /* 1728 */

// ---------------- scratch (device globals) ----------------
__device__ uint4  g_Qc[(size_t)NL*QN*SS*ROWB/16];
__device__ uint4  g_Kc[(size_t)NL*KN*SS*ROWB/16];
__device__ __align__(16) __half g_Mh[AELEM];
__device__ __align__(16) __half g_Fh[AELEM];
__device__ __align__(16) __half g_W1h[NL*DH*DH];
__device__ __align__(16) __half g_W2h[NL*DFFN*SS];
__device__ __align__(16) float g_GT[NL * SS * SS];
__device__ float  g_Xr[(size_t)NL * NP * 2 * SS];
__device__ __align__(16) __half g_Xh[(size_t)NL * NP * 2 * SS];
__device__ float  g_Z [NL * NP * 2];
__device__ unsigned int g_mdone;

__device__ __forceinline__ uint32_t smem_u32(const void* p) {
    uint32_t a;
    asm("{ .reg .u64 t; cvta.to.shared.u64 t, %1; cvt.u32.u64 %0, t; }" : "=r"(a) : "l"(p));
    return a;
}

// ---------------- mma / ldmatrix wrappers ----------------
__device__ __forceinline__ void mma_fp16(float* d, const uint32_t* a, uint32_t b0, uint32_t b1) {
    asm volatile("mma.sync.aligned.m16n8k16.row.col.f32.f16.f16.f32 "
                 "{%0,%1,%2,%3}, {%4,%5,%6,%7}, {%8,%9}, {%0,%1,%2,%3};"
                 : "+f"(d[0]), "+f"(d[1]), "+f"(d[2]), "+f"(d[3])
                 : "r"(a[0]), "r"(a[1]), "r"(a[2]), "r"(a[3]), "r"(b0), "r"(b1));
}
__device__ __forceinline__ void ldsm_x4(uint32_t* r, uint32_t addr) {
    asm volatile("ldmatrix.sync.aligned.m8n8.x4.shared.b16 {%0,%1,%2,%3}, [%4];"
                 : "=r"(r[0]), "=r"(r[1]), "=r"(r[2]), "=r"(r[3]) : "r"(addr));
}

// ---------------- kernel 1: prep ----------------
__device__ __forceinline__ void cvt8(const float* __restrict__ src, __half* dst, int u) {
    float4 f0 = ((const float4*)src)[u * 2];
    float4 f1 = ((const float4*)src)[u * 2 + 1];
    __half2 a0 = __floats2half2_rn(f0.x, f0.y);
    __half2 a1 = __floats2half2_rn(f0.z, f0.w);
    __half2 a2 = __floats2half2_rn(f1.x, f1.y);
    __half2 a3 = __floats2half2_rn(f1.z, f1.w);
    uint4 v;
    v.x = *reinterpret_cast<uint32_t*>(&a0);
    v.y = *reinterpret_cast<uint32_t*>(&a1);
    v.z = *reinterpret_cast<uint32_t*>(&a2);
    v.w = *reinterpret_cast<uint32_t*>(&a3);
    ((uint4*)dst)[u] = v;
}

__global__ void prep_kernel(const float* __restrict__ mem, const float* __restrict__ feat,
                            const float* __restrict__ w1, const float* __restrict__ w2,
                            const float* __restrict__ se)
{
    int idx = blockIdx.x * blockDim.x + threadIdx.x;
    if (idx < CA_U4)                       cvt8(mem,  g_Mh,  idx);
    else if (idx < 2*CA_U4)                cvt8(feat, g_Fh,  idx - CA_U4);
    else if (idx < 2*CA_U4 + W1_U4)        cvt8(w1,   g_W1h, idx - 2*CA_U4);
    else if (idx < PREP_N)                 cvt8(w2,   g_W2h, idx - 2*CA_U4 - W1_U4);
    if (idx < NL * SS * SS) {
        int i = idx / (SS * SS);
        int rem = idx - i * SS * SS;
        int t = rem / SS, s = rem - t * SS;
        g_GT[idx] = 1.0f / (1.0f + expf(-se[i * SS * SS + s * SS + t]));
    }
    if (idx < NL * NP * 2) g_Z[idx] = 0.0f;
    if (idx == 0)          g_mdone = 0u;
}

// ---------------- kernel 2: projection GEMM (HMMA, fp16 in, both dsts) ----------------
#define PCH 8
#define PSTG 32768

__global__ void __launch_bounds__(256)
proj_mma_kernel(const float* __restrict__ bias)
{
    extern __shared__ __align__(128) char psm[];
    const int z = blockIdx.z;
    const int i = (z < NL) ? z : z - NL;
    const int dst = (z >= NL);
    const __half* Ah = (dst ? g_Fh : g_Mh) + i * DH;
    const __half* Wh = g_W1h + (size_t)i * DH * DH;
    const float* bb = bias + i * DH;
    const int LDA = NL * DH;
    char* outBase = (char*)(dst ? g_Kc : g_Qc) + (size_t)(i * QN * SS) * ROWB;
    const int m0 = blockIdx.y * 128, n0 = blockIdx.x * 128;
    const int tid = threadIdx.x, wid = tid >> 5, lane = tid & 31;
    uint32_t sb = smem_u32(psm);
    const int mw = wid >> 2, nw = wid & 3;
    const int m0w = mw * 64, n0w = nw * 32;

    uint32_t baseA[4], baseB[2];
#pragma unroll
    for (int mi = 0; mi < 4; mi++) {
        uint32_t row = (uint32_t)(m0w + mi * 16 + (lane & 15));
        uint32_t off = row * 128 + ((lane >> 4) << 4);
        baseA[mi] = off ^ ((off >> 3) & 0x70);
    }
#pragma unroll
    for (int nj = 0; nj < 2; nj++) {
        uint32_t row = (uint32_t)(n0w + nj * 16 + (lane & 7) + ((lane >> 4) << 3));
        uint32_t off = row * 128 + (((lane >> 3) & 1) << 4);
        baseB[nj] = 16384u + (off ^ ((off >> 3) & 0x70));
    }

    float acc[4][4][4];
#pragma unroll
    for (int mi = 0; mi < 4; mi++)
#pragma unroll
        for (int n8 = 0; n8 < 4; n8++)
#pragma unroll
            for (int j = 0; j < 4; j++) acc[mi][n8][j] = 0.0f;

    uint4 stg[8];
    auto load_chunk = [&](int c) {
        const int co0 = c * 64;
#pragma unroll
        for (int u = 0; u < 8; u++) {
            int idx = tid + u * 256;
            int isW = idx >= 1024;
            int j = idx & 1023;
            int r = j >> 3, g = j & 7;
            const __half* src = isW ? (Wh + (size_t)(n0 + r) * DH  + co0 + g * 8)
                                    : (Ah + (size_t)(m0 + r) * LDA + co0 + g * 8);
            stg[u] = *(const uint4*)src;
        }
    };
    auto store_chunk = [&](int buf) {
#pragma unroll
        for (int u = 0; u < 8; u++) {
            int idx = tid + u * 256;
            int isW = idx >= 1024;
            int j = idx & 1023;
            int r = j >> 3, g = j & 7;
            uint32_t off = (uint32_t)(r * 128 + g * 16);
            off ^= (off >> 3) & 0x70;
            *(uint4*)(psm + buf * PSTG + (isW ? 16384 : 0) + off) = stg[u];
        }
    };

    load_chunk(0);
    int buf = 0;
    for (int c = 0; c < PCH; c++) {
        store_chunk(buf);
        __syncthreads();
        if (c + 1 < PCH) load_chunk(c + 1);

        uint32_t stage = sb + buf * PSTG;
#pragma unroll
        for (int ks = 0; ks < 4; ks++) {
            uint32_t kx = (uint32_t)(ks << 5);
            uint32_t a[4][4], b[2][4];
#pragma unroll
            for (int mi = 0; mi < 4; mi++) ldsm_x4(a[mi], stage + (baseA[mi] ^ kx));
#pragma unroll
            for (int nj = 0; nj < 2; nj++) ldsm_x4(b[nj], stage + (baseB[nj] ^ kx));
#pragma unroll
            for (int mi = 0; mi < 4; mi++)
#pragma unroll
                for (int n8 = 0; n8 < 4; n8++)
                    mma_fp16(acc[mi][n8], a[mi], b[n8 >> 1][(n8 & 1) * 2], b[n8 >> 1][(n8 & 1) * 2 + 1]);
        }
        buf ^= 1;
    }

    const int g8 = lane >> 2, t4 = lane & 3;
    float bv[8];
#pragma unroll
    for (int n8 = 0; n8 < 4; n8++) {
        bv[n8 * 2]     = bb[n0 + n0w + n8 * 8 + t4 * 2];
        bv[n8 * 2 + 1] = bb[n0 + n0w + n8 * 8 + t4 * 2 + 1];
    }
#pragma unroll
    for (int mi = 0; mi < 4; mi++) {
        int r0 = m0 + m0w + mi * 16 + g8;
#pragma unroll
        for (int n8 = 0; n8 < 4; n8++) {
            int c0 = n0 + n0w + n8 * 8 + t4 * 2;
            __half2 v0 = __floats2half2_rn(acc[mi][n8][0] + bv[n8 * 2], acc[mi][n8][1] + bv[n8 * 2 + 1]);
            __half2 v1 = __floats2half2_rn(acc[mi][n8][2] + bv[n8 * 2], acc[mi][n8][3] + bv[n8 * 2 + 1]);
            *(__half2*)(outBase + (size_t)r0 * ROWB + c0 * 2)       = v0;
            *(__half2*)(outBase + (size_t)(r0 + 8) * ROWB + c0 * 2) = v1;
        }
    }
}

// ---------------- kernel 3: HMMA score GEMM + gate + dual max-pool ----------------
#define STAGES 3
#define CHUNK_B 128
#define NCHUNK 8
#define TILE_A 24576
#define STAGE_BYTES 36864
#define SM_BASE 1024
#define SMEM_TOTAL_SCORE (SM_BASE + STAGES * STAGE_BYTES)

__global__ void __launch_bounds__(192, 2)
score_mma_kernel(const float* __restrict__ g1, const float* __restrict__ bb1)
{
    extern __shared__ __align__(128) char dsm[];
    const int i = blockIdx.z, q = blockIdx.y;
    const int k = blockIdx.x >> 1;
    const int h = blockIdx.x & 1;
    const int tid = threadIdx.x;
    const int wid = tid >> 5;
    const int lane = tid & 31;
    uint32_t sb = smem_u32(dsm);

    const char* aG = (const char*)g_Qc + (size_t)((i * QN + q) * SS) * ROWB;
    const char* bG = (const char*)g_Kc + (size_t)((i * KN + k) * SS + h * 96) * ROWB;

    const int mw = wid >> 1, nw = wid & 1;
    const int m0 = mw * 64;
    const int n0 = nw * 48;

    uint32_t baseA[4], baseB[3];
#pragma unroll
    for (int mi = 0; mi < 4; mi++) {
        uint32_t row = (uint32_t)(m0 + mi * 16 + (lane & 15));
        uint32_t off = row * 128 + ((lane >> 4) << 4);
        baseA[mi] = off ^ ((off >> 3) & 0x70);
    }
#pragma unroll
    for (int nt = 0; nt < 3; nt++) {
        uint32_t row = (uint32_t)(n0 + nt * 16 + (lane & 7) + ((lane >> 4) << 3));
        uint32_t off = row * 128 + (((lane >> 3) & 1) << 4);
        baseB[nt] = TILE_A + (off ^ ((off >> 3) & 0x70));
    }

    float acc[4][6][4];
#pragma unroll
    for (int mi = 0; mi < 4; mi++)
#pragma unroll
        for (int ni = 0; ni < 6; ni++)
#pragma unroll
            for (int j = 0; j < 4; j++) acc[mi][ni][j] = 0.0f;

    auto load_stage = [&](int c, int st) {
        uint32_t base = sb + SM_BASE + st * STAGE_BYTES;
#pragma unroll
        for (int l = 0; l < 12; l++) {
            int idx = tid + l * 192;
            int isB = idx >= 1536;
            int j2 = isB ? idx - 1536 : idx;
            int r = j2 >> 3, g = j2 & 7;
            uint32_t off = (uint32_t)(r * 128 + g * 16);
            off ^= (off >> 3) & 0x70;
            uint32_t dst = base + (isB ? TILE_A : 0) + off;
            const void* src = (const void*)((isB ? bG : aG) + (size_t)r * ROWB + c * CHUNK_B + g * 16);
            asm volatile("cp.async.cg.shared.global [%0], [%1], 16;" :: "r"(dst), "l"(src) : "memory");
        }
        asm volatile("cp.async.commit_group;" ::: "memory");
    };

    load_stage(0, 0);
    load_stage(1, 1);

    int stc = 0, stl = 2;
    for (int it = 0; it < NCHUNK; it++) {
        if (it == NCHUNK - 1) asm volatile("cp.async.wait_group 0;" ::: "memory");
        else                  asm volatile("cp.async.wait_group 1;" ::: "memory");
        __syncthreads();
        if (it + 2 < NCHUNK) load_stage(it + 2, stl);

        uint32_t stage = sb + SM_BASE + stc * STAGE_BYTES;
#pragma unroll
        for (int ks = 0; ks < 4; ks++) {
            uint32_t kx = (uint32_t)(ks << 5);
            uint32_t a[4][4], b[3][4];
#pragma unroll
            for (int mi = 0; mi < 4; mi++) ldsm_x4(a[mi], stage + (baseA[mi] ^ kx));
#pragma unroll
            for (int nt = 0; nt < 3; nt++) ldsm_x4(b[nt], stage + (baseB[nt] ^ kx));
#pragma unroll
            for (int mi = 0; mi < 4; mi++) {
#pragma unroll
                for (int nt = 0; nt < 3; nt++) {
                    mma_fp16(acc[mi][2 * nt],     a[mi], b[nt][0], b[nt][1]);
                    mma_fp16(acc[mi][2 * nt + 1], a[mi], b[nt][2], b[nt][3]);
                }
            }
        }
        if (++stc == STAGES) stc = 0;
        if (++stl == STAGES) stl = 0;
    }

    // ---- epilogue: transposed gate + dual max-pool ----
    const float* gtb = g_GT + (size_t)i * SS * SS;
    const int g8 = lane >> 2, t4 = lane & 3;
    float rmax[8], cmax[12];
#pragma unroll
    for (int j = 0; j < 8; j++)  rmax[j] = -3.402823466e38f;
#pragma unroll
    for (int j = 0; j < 12; j++) cmax[j] = -3.402823466e38f;

#pragma unroll
    for (int mi = 0; mi < 4; mi++) {
        int r0 = m0 + mi * 16 + g8;
        int r1 = r0 + 8;
#pragma unroll
        for (int ni = 0; ni < 6; ni++) {
            int c0 = h * 96 + n0 + ni * 8 + t4 * 2;
            float2 gA = *(const float2*)(gtb + (size_t)r0 * SS + c0);
            float2 gB = *(const float2*)(gtb + (size_t)r1 * SS + c0);
            float v00 = acc[mi][ni][0] * gA.x;
            float v01 = acc[mi][ni][1] * gA.y;
            float v10 = acc[mi][ni][2] * gB.x;
            float v11 = acc[mi][ni][3] * gB.y;
            rmax[mi * 2]     = fmaxf(rmax[mi * 2],     fmaxf(v00, v01));
            rmax[mi * 2 + 1] = fmaxf(rmax[mi * 2 + 1], fmaxf(v10, v11));
            cmax[ni * 2]     = fmaxf(cmax[ni * 2],     fmaxf(v00, v10));
            cmax[ni * 2 + 1] = fmaxf(cmax[ni * 2 + 1], fmaxf(v01, v11));
        }
    }
#pragma unroll
    for (int m = 1; m <= 2; m <<= 1)
#pragma unroll
        for (int j = 0; j < 8; j++)
            rmax[j] = fmaxf(rmax[j], __shfl_xor_sync(0xffffffffu, rmax[j], m));
#pragma unroll
    for (int m = 4; m <= 16; m <<= 1)
#pragma unroll
        for (int j = 0; j < 12; j++)
            cmax[j] = fmaxf(cmax[j], __shfl_xor_sync(0xffffffffu, cmax[j], m));

    float* red1 = (float*)(dsm + SM_BASE);
    float* red2 = red1 + 2 * SS;
    if (t4 == 0) {
#pragma unroll
        for (int j = 0; j < 8; j++)
            red1[nw * SS + m0 + (j >> 1) * 16 + g8 + (j & 1) * 8] = rmax[j];
    }
    if (g8 == 0) {
#pragma unroll
        for (int j = 0; j < 12; j++)
            red2[mw * 96 + n0 + (j >> 1) * 8 + t4 * 2 + (j & 1)] = cmax[j];
    }
    __syncthreads();

    const size_t pair = (size_t)i * NP + (size_t)q * KN + k;
    {
        float m = fmaxf(red1[tid], red1[SS + tid]);
        g_Xr[(pair * 2 + h) * SS + tid] = m;
    }
    if (tid < 96) {
        const float scale = 1.0f / sqrtf(1.0f + 1e-5f);
        float g1c = g1[i] * scale, b1v = bb1[i];
        float m = fmaxf(fmaxf(red2[tid], red2[96 + tid]), red2[192 + tid]);
        g_Xh[(pair * 2 + 1) * SS + h * 96 + tid] = __float2half_rn(m * g1c + b1v);
    }
}

// ---------------- kernel 3b: merge row-max halves + bn1 -> fp16 X ----------------
__global__ void merge_x_kernel(const float* __restrict__ g1, const float* __restrict__ bb1) {
    int idx = blockIdx.x * blockDim.x + threadIdx.x;
    if (idx >= NL * NP * SS) return;
    const float scale = 1.0f / sqrtf(1.0f + 1e-5f);
    int i = idx / (NP * SS);
    float g1c = g1[i] * scale, b1v = bb1[i];
    size_t pair = (size_t)(idx / SS);
    int t = idx - (int)(pair * SS);
    float rm = fmaxf(g_Xr[(pair * 2) * SS + t], g_Xr[(pair * 2 + 1) * SS + t]);
    g_Xh[(pair * 2) * SS + t] = __float2half_rn(rm * g1c + b1v);
}

// ---------------- kernel 4: HMMA mlp + fused final ----------------
#define MCH 3
#define MSTG 32768

__global__ void __launch_bounds__(256)
mlp_mma_kernel(const float* __restrict__ b2,
               const float* __restrict__ g2, const float* __restrict__ bb2,
               const float* __restrict__ w3,
               const float* __restrict__ fc3_b,
               const float* __restrict__ bn3_g, const float* __restrict__ bn3_b,
               const float* __restrict__ norm_g, const float* __restrict__ norm_b,
               float* __restrict__ out)
{
    extern __shared__ __align__(128) char msm[];
    __shared__ float zsh[128];
    __shared__ unsigned int mflag;
    const int i = blockIdx.z;
    const int row0 = blockIdx.y * 128;
    const int col0 = blockIdx.x * 128;
    const float scale = 1.0f / sqrtf(1.0f + 1e-5f);
    const __half* W2h = g_W2h + (size_t)i * DFFN * SS;
    const __half* Xh = g_Xh + (size_t)i * NP * 2 * SS;
    const int tid = threadIdx.x, wid = tid >> 5, lane = tid & 31;
    uint32_t sb = smem_u32(msm);
    const int mw = wid >> 2, nw = wid & 3;
    const int m0w = mw * 64, n0w = nw * 32;
    if (tid < 128) zsh[tid] = 0.0f;

    uint32_t baseA[4], baseB[2];
#pragma unroll
    for (int mi = 0; mi < 4; mi++) {
        uint32_t row = (uint32_t)(m0w + mi * 16 + (lane & 15));
        uint32_t off = row * 128 + ((lane >> 4) << 4);
        baseA[mi] = off ^ ((off >> 3) & 0x70);
    }
#pragma unroll
    for (int nj = 0; nj < 2; nj++) {
        uint32_t row = (uint32_t)(n0w + nj * 16 + (lane & 7) + ((lane >> 4) << 3));
        uint32_t off = row * 128 + (((lane >> 3) & 1) << 4);
        baseB[nj] = 16384u + (off ^ ((off >> 3) & 0x70));
    }

    float acc[4][4][4];
#pragma unroll
    for (int mi = 0; mi < 4; mi++)
#pragma unroll
        for (int n8 = 0; n8 < 4; n8++)
#pragma unroll
            for (int j = 0; j < 4; j++) acc[mi][n8][j] = 0.0f;

    uint4 stg[8];
    auto load_chunk = [&](int c) {
        const int kk0 = c * 64;
#pragma unroll
        for (int u = 0; u < 8; u++) {
            int idx = tid + u * 256;
            int isW = idx >= 1024;
            int j = idx & 1023;
            int r = j >> 3, g = j & 7;
            const __half* src = isW ? (W2h + (size_t)(col0 + r) * SS + kk0 + g * 8)
                                    : (Xh  + (size_t)(row0 + r) * SS + kk0 + g * 8);
            stg[u] = *(const uint4*)src;
        }
    };
    auto store_chunk = [&](int buf) {
#pragma unroll
        for (int u = 0; u < 8; u++) {
            int idx = tid + u * 256;
            int isW = idx >= 1024;
            int j = idx & 1023;
            int r = j >> 3, g = j & 7;
            uint32_t off = (uint32_t)(r * 128 + g * 16);
            off ^= (off >> 3) & 0x70;
            *(uint4*)(msm + buf * MSTG + (isW ? 16384 : 0) + off) = stg[u];
        }
    };

    load_chunk(0);
    int buf = 0;
    for (int c = 0; c < MCH; c++) {
        store_chunk(buf);
        __syncthreads();
        if (c + 1 < MCH) load_chunk(c + 1);

        uint32_t stage = sb + buf * MSTG;
#pragma unroll
        for (int ks = 0; ks < 4; ks++) {
            uint32_t kx = (uint32_t)(ks << 5);
            uint32_t a[4][4], b[2][4];
#pragma unroll
            for (int mi = 0; mi < 4; mi++) ldsm_x4(a[mi], stage + (baseA[mi] ^ kx));
#pragma unroll
            for (int nj = 0; nj < 2; nj++) ldsm_x4(b[nj], stage + (baseB[nj] ^ kx));
#pragma unroll
            for (int mi = 0; mi < 4; mi++)
#pragma unroll
                for (int n8 = 0; n8 < 4; n8++)
                    mma_fp16(acc[mi][n8], a[mi], b[n8 >> 1][(n8 & 1) * 2], b[n8 >> 1][(n8 & 1) * 2 + 1]);
        }
        buf ^= 1;
    }

    const int g8 = lane >> 2, t4 = lane & 3;
    float b2v[8], g2v[8], bb2v[8], w3v[8];
#pragma unroll
    for (int n8 = 0; n8 < 4; n8++) {
        int c0 = col0 + n0w + n8 * 8 + t4 * 2;
        b2v[n8*2]   = __ldg(b2  + (size_t)i * DFFN + c0);
        b2v[n8*2+1] = __ldg(b2  + (size_t)i * DFFN + c0 + 1);
        g2v[n8*2]   = __ldg(g2  + (size_t)i * DFFN + c0);
        g2v[n8*2+1] = __ldg(g2  + (size_t)i * DFFN + c0 + 1);
        bb2v[n8*2]   = __ldg(bb2 + (size_t)i * DFFN + c0);
        bb2v[n8*2+1] = __ldg(bb2 + (size_t)i * DFFN + c0 + 1);
        w3v[n8*2]   = __ldg(w3  + (size_t)i * DFFN + c0);
        w3v[n8*2+1] = __ldg(w3  + (size_t)i * DFFN + c0 + 1);
    }
    __syncthreads();

#pragma unroll
    for (int mi = 0; mi < 4; mi++) {
        float zp0 = 0.0f, zp1 = 0.0f;
#pragma unroll
        for (int n8 = 0; n8 < 4; n8++) {
#pragma unroll
            for (int e = 0; e < 2; e++) {
                float y0 = acc[mi][n8][e]     + b2v[n8*2+e];
                float y1 = acc[mi][n8][2 + e] + b2v[n8*2+e];
                float yb0 = y0 * (g2v[n8*2+e] * scale) + bb2v[n8*2+e];
                float yb1 = y1 * (g2v[n8*2+e] * scale) + bb2v[n8*2+e];
                if (yb0 > 0.0f) zp0 += yb0 * w3v[n8*2+e];
                if (yb1 > 0.0f) zp1 += yb1 * w3v[n8*2+e];
            }
        }
        zp0 += __shfl_xor_sync(0xffffffffu, zp0, 1);
        zp0 += __shfl_xor_sync(0xffffffffu, zp0, 2);
        zp1 += __shfl_xor_sync(0xffffffffu, zp1, 1);
        zp1 += __shfl_xor_sync(0xffffffffu, zp1, 2);
        if (t4 == 0) {
            atomicAdd(&zsh[m0w + mi * 16 + g8], zp0);
            atomicAdd(&zsh[m0w + mi * 16 + g8 + 8], zp1);
        }
    }
    __syncthreads();
    if (tid < 128) atomicAdd(&g_Z[(size_t)i * NP * 2 + row0 + tid], zsh[tid]);

    // ---- fused final: last block computes the output ----
    __syncthreads();
    if (tid == 0) {
        __threadfence();
        mflag = atomicAdd(&g_mdone, 1u);
    }
    __syncthreads();
    if (mflag == MLP_BLOCKS - 1) {
        __threadfence();
        for (int p = tid; p < NP; p += 256) {
            float accv = 0.0f;
#pragma unroll
            for (int ii = 0; ii < NL; ii++) {
                float u = g_Z[ii * NP * 2 + 2 * p] + g_Z[ii * NP * 2 + 2 * p + 1] + 2.0f * fc3_b[ii];
                accv += u * (bn3_g[ii] * scale) + bn3_b[ii];
            }
            out[p] = accv * (norm_g[0] * scale) + norm_b[0];
        }
    }
}

// ---------------- launch ----------------
extern "C" void kernel_launch(void* const* d_in, const int* in_sizes, int n_in,
                              void* d_out, int out_size)
{
    (void)in_sizes; (void)n_in; (void)out_size;
    const float* memory_  = (const float*)d_in[0];
    const float* features = (const float*)d_in[1];
    const float* fc1_w  = (const float*)d_in[2];
    const float* fc1_b  = (const float*)d_in[3];
    const float* se     = (const float*)d_in[4];
    const float* bn1_g  = (const float*)d_in[5];
    const float* bn1_b  = (const float*)d_in[6];
    const float* fc2_w  = (const float*)d_in[7];
    const float* fc2_b  = (const float*)d_in[8];
    const float* bn2_g  = (const float*)d_in[9];
    const float* bn2_b  = (const float*)d_in[10];
    const float* fc3_w  = (const float*)d_in[11];
    const float* fc3_b  = (const float*)d_in[12];
    const float* bn3_g  = (const float*)d_in[13];
    const float* bn3_b  = (const float*)d_in[14];
    const float* norm_g = (const float*)d_in[15];
    const float* norm_b = (const float*)d_in[16];
    float* out = (float*)d_out;

    cudaFuncSetAttribute(score_mma_kernel,
                         cudaFuncAttributeMaxDynamicSharedMemorySize, SMEM_TOTAL_SCORE);
    cudaFuncSetAttribute(proj_mma_kernel,
                         cudaFuncAttributeMaxDynamicSharedMemorySize, 2 * PSTG);
    cudaFuncSetAttribute(mlp_mma_kernel,
                         cudaFuncAttributeMaxDynamicSharedMemorySize, 2 * MSTG);

    prep_kernel<<<(PREP_N + 255) / 256, 256>>>(memory_, features, fc1_w, fc2_w, se);

    proj_mma_kernel<<<dim3(DH / 128, (QN * SS) / 128, 2 * NL), 256, 2 * PSTG>>>(fc1_b);

    score_mma_kernel<<<dim3(KN * 2, QN, NL), 192, SMEM_TOTAL_SCORE>>>(bn1_g, bn1_b);

    merge_x_kernel<<<(NL * NP * SS + 255) / 256, 256>>>(bn1_g, bn1_b);

    mlp_mma_kernel<<<dim3(DFFN / 128, (2 * NP) / 128, NL), 256, 2 * MSTG>>>(
        fc2_b, bn2_g, bn2_b, fc3_w, fc3_b, bn3_g, bn3_b, norm_g, norm_b, out);
}